// round 1
// baseline (speedup 1.0000x reference)
#include <cuda_runtime.h>
#include <cuda_bf16.h>

#define N_NODES 50000
#define IN_CH   64
#define REL_DIM 32
#define N_EDGES 800000
#define NEG_SLOPE 0.01f

// ---------------- scratch (device globals; no allocation allowed) ----------------
__device__ float    g_e    [(size_t)N_EDGES * IN_CH];   // 204.8 MB edge features
__device__ float    g_ew1  [N_EDGES];                    // e . c1_ew_w + b
__device__ float    g_ew2  [N_EDGES];                    // e . c2_ew_w + b
__device__ float    g_alpha[N_EDGES];                    // alpha -> exp(alpha-m)
__device__ float    g_x    [N_NODES * IN_CH];            // transformed node feats
__device__ float    g_h    [N_NODES * IN_CH];            // layer-1 output
__device__ float    g_ai   [N_NODES];
__device__ float    g_aj   [N_NODES];
__device__ unsigned g_mkey [N_NODES];
__device__ float    g_ssum [N_NODES];

// order-preserving float -> uint key (monotone total order)
__device__ __forceinline__ unsigned fkey(float f) {
    unsigned b = __float_as_uint(f);
    return (b & 0x80000000u) ? ~b : (b | 0x80000000u);
}
__device__ __forceinline__ float funkey(unsigned u) {
    unsigned b = (u & 0x80000000u) ? (u & 0x7fffffffu) : ~u;
    return __uint_as_float(b);
}

// ---------------- K0: e = r@relWt + relB ; ew1, ew2 scalars -----------------------
// warp per edge; lane k holds r[k]; lane computes channels {lane, lane+32}
__global__ void k_edge_feat(const float* __restrict__ r,
                            const float* __restrict__ relW,  // [64,32]
                            const float* __restrict__ relB,  // [64]
                            const float* __restrict__ ew1w, const float* __restrict__ ew1b,
                            const float* __restrict__ ew2w, const float* __restrict__ ew2b)
{
    __shared__ float Wt[REL_DIM * IN_CH];   // Wt[k*64+c] = relW[c*32+k]
    __shared__ float bs[IN_CH], w1s[IN_CH], w2s[IN_CH];
    int tid = threadIdx.x;
    for (int i = tid; i < REL_DIM * IN_CH; i += 256) {
        int c = i >> 5, k = i & 31;
        Wt[k * IN_CH + c] = relW[i];
    }
    if (tid < IN_CH) { bs[tid] = relB[tid]; w1s[tid] = ew1w[tid]; w2s[tid] = ew2w[tid]; }
    __syncthreads();

    int lane = tid & 31;
    int e = blockIdx.x * 8 + (tid >> 5);
    if (e >= N_EDGES) return;

    float rv = r[(size_t)e * REL_DIM + lane];
    float acc0 = bs[lane], acc1 = bs[32 + lane];
#pragma unroll
    for (int k = 0; k < 32; k++) {
        float v = __shfl_sync(0xffffffffu, rv, k);
        acc0 += v * Wt[k * IN_CH + lane];
        acc1 += v * Wt[k * IN_CH + 32 + lane];
    }
    size_t base = (size_t)e * IN_CH;
    g_e[base + lane]      = acc0;
    g_e[base + 32 + lane] = acc1;

    float p1 = acc0 * w1s[lane] + acc1 * w1s[32 + lane];
    float p2 = acc0 * w2s[lane] + acc1 * w2s[32 + lane];
#pragma unroll
    for (int o = 16; o > 0; o >>= 1) {
        p1 += __shfl_xor_sync(0xffffffffu, p1, o);
        p2 += __shfl_xor_sync(0xffffffffu, p2, o);
    }
    if (lane == 0) { g_ew1[e] = p1 + ew1b[0]; g_ew2[e] = p2 + ew2b[0]; }
}

// ---------------- K1: node transform + per-node attention scalars ----------------
// warp per node; x = in@Wt + b ; ai[n] = x.ai_w + ai_b ; aj[n] = x.aj_w + aj_b
__global__ void k_node_transform(const float* __restrict__ in,
                                 const float* __restrict__ W,  // [64,64]
                                 const float* __restrict__ b,
                                 const float* __restrict__ aiw, const float* __restrict__ aib,
                                 const float* __restrict__ ajw, const float* __restrict__ ajb)
{
    __shared__ float Wt[IN_CH * IN_CH];   // Wt[k*64+c] = W[c*64+k]
    __shared__ float bsh[IN_CH], ais[IN_CH], ajs[IN_CH];
    int tid = threadIdx.x;
    for (int i = tid; i < IN_CH * IN_CH; i += 256) {
        int c = i >> 6, k = i & 63;
        Wt[k * IN_CH + c] = W[i];
    }
    if (tid < IN_CH) { bsh[tid] = b[tid]; ais[tid] = aiw[tid]; ajs[tid] = ajw[tid]; }
    __syncthreads();

    int lane = tid & 31;
    int n = blockIdx.x * 8 + (tid >> 5);
    if (n >= N_NODES) return;

    float iv0 = in[(size_t)n * IN_CH + lane];
    float iv1 = in[(size_t)n * IN_CH + 32 + lane];
    float acc0 = bsh[lane], acc1 = bsh[32 + lane];
#pragma unroll
    for (int k = 0; k < 32; k++) {
        float v = __shfl_sync(0xffffffffu, iv0, k);
        acc0 += v * Wt[k * IN_CH + lane];
        acc1 += v * Wt[k * IN_CH + 32 + lane];
    }
#pragma unroll
    for (int k = 0; k < 32; k++) {
        float v = __shfl_sync(0xffffffffu, iv1, k);
        acc0 += v * Wt[(k + 32) * IN_CH + lane];
        acc1 += v * Wt[(k + 32) * IN_CH + 32 + lane];
    }
    g_x[(size_t)n * IN_CH + lane]      = acc0;
    g_x[(size_t)n * IN_CH + 32 + lane] = acc1;

    float ap = acc0 * ais[lane] + acc1 * ais[32 + lane];
    float jp = acc0 * ajs[lane] + acc1 * ajs[32 + lane];
#pragma unroll
    for (int o = 16; o > 0; o >>= 1) {
        ap += __shfl_xor_sync(0xffffffffu, ap, o);
        jp += __shfl_xor_sync(0xffffffffu, jp, o);
    }
    if (lane == 0) { g_ai[n] = ap + aib[0]; g_aj[n] = jp + ajb[0]; }
}

// ---------------- zero: mkey, ssum, out accumulator ------------------------------
__global__ void k_zero(float* __restrict__ out)
{
    int i = blockIdx.x * blockDim.x + threadIdx.x;
    if (i < N_NODES) { g_mkey[i] = 0u; g_ssum[i] = 0.0f; }
    int total = N_NODES * IN_CH;
    int stride = gridDim.x * blockDim.x;
    for (int j = i; j < total; j += stride) out[j] = 0.0f;
}

// ---------------- K2: alpha = leaky(ai[dst] + aj[src] + ew); segment max over src -
__global__ void k_alpha_max(const int* __restrict__ src, const int* __restrict__ dst,
                            const float* __restrict__ ew)
{
    int i = blockIdx.x * blockDim.x + threadIdx.x;
    if (i >= N_EDGES) return;
    int s = src[i], d = dst[i];
    float a = g_ai[d] + g_aj[s] + ew[i];
    a = a > 0.0f ? a : NEG_SLOPE * a;
    g_alpha[i] = a;
    atomicMax(&g_mkey[s], fkey(a));
}

// ---------------- K3: ex = exp(alpha - m[src]); segment sum over src -------------
__global__ void k_exp_sum(const int* __restrict__ src)
{
    int i = blockIdx.x * blockDim.x + threadIdx.x;
    if (i >= N_EDGES) return;
    int s = src[i];
    float m = funkey(g_mkey[s]);
    float ex = __expf(g_alpha[i] - m);
    g_alpha[i] = ex;
    atomicAdd(&g_ssum[s], ex);
}

// ---------------- K4: msg = coef*(x[src]+e); scatter-add at dst ------------------
// warp per edge; each lane handles 2 channels (float2)
__global__ void k_message(const int* __restrict__ src, const int* __restrict__ dst,
                          float* __restrict__ out)
{
    int lane = threadIdx.x & 31;
    int e = blockIdx.x * 8 + (threadIdx.x >> 5);
    if (e >= N_EDGES) return;
    int s = src[e], d = dst[e];
    float coef = g_alpha[e] / (g_ssum[s] + 1e-16f);
    const float2* ep = reinterpret_cast<const float2*>(g_e + (size_t)e * IN_CH);
    const float2* xp = reinterpret_cast<const float2*>(g_x + (size_t)s * IN_CH);
    float2 ev = ep[lane];
    float2 xv = xp[lane];
    float* o = out + (size_t)d * IN_CH + 2 * lane;
    atomicAdd(o,     coef * (xv.x + ev.x));
    atomicAdd(o + 1, coef * (xv.y + ev.y));
}

// ---------------- K5: in-place relu ----------------------------------------------
__global__ void k_relu(float* __restrict__ p, int n)
{
    int i = blockIdx.x * blockDim.x + threadIdx.x;
    if (i < n) p[i] = fmaxf(p[i], 0.0f);
}

extern "C" void kernel_launch(void* const* d_in, const int* in_sizes, int n_in,
                              void* d_out, int out_size)
{
    const float* feat   = (const float*)d_in[0];
    const int*   eidx   = (const int*)  d_in[1];   // [2, E]
    const float* r      = (const float*)d_in[2];
    const float* rel_w  = (const float*)d_in[3];
    const float* rel_b  = (const float*)d_in[4];
    const float* c1_lw  = (const float*)d_in[5];
    const float* c1_lb  = (const float*)d_in[6];
    const float* c1_aiw = (const float*)d_in[7];
    const float* c1_aib = (const float*)d_in[8];
    const float* c1_ajw = (const float*)d_in[9];
    const float* c1_ajb = (const float*)d_in[10];
    const float* c1_eww = (const float*)d_in[11];
    const float* c1_ewb = (const float*)d_in[12];
    const float* c2_lw  = (const float*)d_in[13];
    const float* c2_lb  = (const float*)d_in[14];
    const float* c2_aiw = (const float*)d_in[15];
    const float* c2_aib = (const float*)d_in[16];
    const float* c2_ajw = (const float*)d_in[17];
    const float* c2_ajb = (const float*)d_in[18];
    const float* c2_eww = (const float*)d_in[19];
    const float* c2_ewb = (const float*)d_in[20];
    float* out = (float*)d_out;

    const int* src = eidx;            // edge_index[0]
    const int* dst = eidx + N_EDGES;  // edge_index[1]

    float* g_h_ptr;   cudaGetSymbolAddress((void**)&g_h_ptr, g_h);
    const float* g_ew1_p; cudaGetSymbolAddress((void**)&g_ew1_p, g_ew1);
    const float* g_ew2_p; cudaGetSymbolAddress((void**)&g_ew2_p, g_ew2);

    const int EB = (N_EDGES + 7) / 8;        // warp-per-edge blocks (256 thr)
    const int ET = (N_EDGES + 255) / 256;    // thread-per-edge blocks
    const int NB = (N_NODES + 7) / 8;        // warp-per-node blocks
    const int ZB = (N_NODES * IN_CH + 255) / 256;

    // edge features + both layers' ew scalars (one pass over r / one write of e)
    k_edge_feat<<<EB, 256>>>(r, rel_w, rel_b, c1_eww, c1_ewb, c2_eww, c2_ewb);

    // ---- layer 1 ----
    k_node_transform<<<NB, 256>>>(feat, c1_lw, c1_lb, c1_aiw, c1_aib, c1_ajw, c1_ajb);
    k_zero<<<ZB, 256>>>(g_h_ptr);
    k_alpha_max<<<ET, 256>>>(src, dst, g_ew1_p);
    k_exp_sum<<<ET, 256>>>(src);
    k_message<<<EB, 256>>>(src, dst, g_h_ptr);
    k_relu<<<ZB, 256>>>(g_h_ptr, N_NODES * IN_CH);

    // ---- layer 2 ----
    k_node_transform<<<NB, 256>>>(g_h_ptr, c2_lw, c2_lb, c2_aiw, c2_aib, c2_ajw, c2_ajb);
    k_zero<<<ZB, 256>>>(out);
    k_alpha_max<<<ET, 256>>>(src, dst, g_ew2_p);
    k_exp_sum<<<ET, 256>>>(src);
    k_message<<<EB, 256>>>(src, dst, out);
    k_relu<<<ZB, 256>>>(out, N_NODES * IN_CH);
}

// round 3
// speedup vs baseline: 2.4547x; 2.4547x over previous
#include <cuda_runtime.h>
#include <cuda_bf16.h>

#define N_NODES 50000
#define IN_CH   64
#define REL_DIM 32
#define N_EDGES 800000
#define NEG_SLOPE 0.01f

// ---------------- scratch (device globals) ----------------
__device__ float    g_ew1  [N_EDGES];
__device__ float    g_ew2  [N_EDGES];
__device__ float    g_alpha[N_EDGES];          // alpha, then ex
__device__ float    g_x    [N_NODES * IN_CH];
__device__ float    g_h    [N_NODES * IN_CH];
__device__ float    g_ai   [N_NODES];
__device__ float    g_aj   [N_NODES];
__device__ unsigned g_mkey [N_NODES];
__device__ float    g_ssum [N_NODES];
__device__ int      g_deg  [N_NODES];
__device__ int      g_rowst[N_NODES];
__device__ int      g_curs [N_NODES];
__device__ int      g_perm [N_EDGES];
__device__ float    g_v1   [REL_DIM];
__device__ float    g_v2   [REL_DIM];
__device__ float    g_ewc  [2];

__device__ __forceinline__ unsigned fkey(float f) {
    unsigned b = __float_as_uint(f);
    return (b & 0x80000000u) ? ~b : (b | 0x80000000u);
}
__device__ __forceinline__ float funkey(unsigned u) {
    unsigned b = (u & 0x80000000u) ? (u & 0x7fffffffu) : ~u;
    return __uint_as_float(b);
}

// ---- fold ew linear through rel linear: v = relW^T @ ew_w ; c = relB.ew_w + ew_b
__global__ void k_ewvec(const float* __restrict__ relW, const float* __restrict__ relB,
                        const float* __restrict__ w1, const float* __restrict__ b1,
                        const float* __restrict__ w2, const float* __restrict__ b2)
{
    int t = threadIdx.x;
    if (t < REL_DIM) {
        float a1 = 0.f, a2 = 0.f;
#pragma unroll
        for (int c = 0; c < IN_CH; c++) {
            float w = relW[c * REL_DIM + t];
            a1 += w * w1[c];
            a2 += w * w2[c];
        }
        g_v1[t] = a1; g_v2[t] = a2;
    } else if (t == 32) {
        float s = 0.f;
        for (int c = 0; c < IN_CH; c++) s += relB[c] * w1[c];
        g_ewc[0] = s + b1[0];
    } else if (t == 33) {
        float s = 0.f;
        for (int c = 0; c < IN_CH; c++) s += relB[c] * w2[c];
        g_ewc[1] = s + b2[0];
    }
}

// ---- ew1/ew2 per edge: one streaming pass over r
__global__ void k_ew(const float* __restrict__ r)
{
    __shared__ float sv1[REL_DIM], sv2[REL_DIM], sc[2];
    int t = threadIdx.x;
    if (t < REL_DIM) { sv1[t] = g_v1[t]; sv2[t] = g_v2[t]; }
    if (t < 2) sc[t] = g_ewc[t];
    __syncthreads();
    int e = blockIdx.x * 256 + t;
    if (e >= N_EDGES) return;
    const float4* rp = reinterpret_cast<const float4*>(r + (size_t)e * REL_DIM);
    float a1 = 0.f, a2 = 0.f;
#pragma unroll
    for (int q = 0; q < 8; q++) {
        float4 f = rp[q];
        a1 += f.x * sv1[4*q] + f.y * sv1[4*q+1] + f.z * sv1[4*q+2] + f.w * sv1[4*q+3];
        a2 += f.x * sv2[4*q] + f.y * sv2[4*q+1] + f.z * sv2[4*q+2] + f.w * sv2[4*q+3];
    }
    g_ew1[e] = a1 + sc[0];
    g_ew2[e] = a2 + sc[1];
}

// ---- CSR build (counting sort by dst) -------------------------------------------
__global__ void k_zero_deg()
{
    int i = blockIdx.x * blockDim.x + threadIdx.x;
    if (i < N_NODES) g_deg[i] = 0;
}
__global__ void k_hist(const int* __restrict__ dst)
{
    int i = blockIdx.x * blockDim.x + threadIdx.x;
    if (i < N_EDGES) atomicAdd(&g_deg[dst[i]], 1);
}
__global__ void k_scan()
{
    __shared__ int wsum[32];
    __shared__ int carry_s;
    int t = threadIdx.x, lane = t & 31, wid = t >> 5;
    if (t == 0) carry_s = 0;
    __syncthreads();
    for (int base = 0; base < N_NODES; base += 1024) {
        int i = base + t;
        int v = (i < N_NODES) ? g_deg[i] : 0;
        int x = v;
#pragma unroll
        for (int off = 1; off < 32; off <<= 1) {
            int y = __shfl_up_sync(0xffffffffu, x, off);
            if (lane >= off) x += y;
        }
        if (lane == 31) wsum[wid] = x;
        __syncthreads();
        if (wid == 0) {
            int s = wsum[lane];
#pragma unroll
            for (int off = 1; off < 32; off <<= 1) {
                int y = __shfl_up_sync(0xffffffffu, s, off);
                if (lane >= off) s += y;
            }
            wsum[lane] = s;
        }
        __syncthreads();
        int warpoff = (wid == 0) ? 0 : wsum[wid - 1];
        int excl = carry_s + warpoff + x - v;
        if (i < N_NODES) { g_rowst[i] = excl; g_curs[i] = excl; }
        __syncthreads();
        if (t == 0) carry_s += wsum[31];
        __syncthreads();
    }
}
__global__ void k_scatter(const int* __restrict__ dst)
{
    int i = blockIdx.x * blockDim.x + threadIdx.x;
    if (i >= N_EDGES) return;
    int p = atomicAdd(&g_curs[dst[i]], 1);
    g_perm[p] = i;
}

// ---- node transform + per-node attention scalars (warp per node) ----------------
__global__ void k_node_transform(const float* __restrict__ in,
                                 const float* __restrict__ W,
                                 const float* __restrict__ b,
                                 const float* __restrict__ aiw, const float* __restrict__ aib,
                                 const float* __restrict__ ajw, const float* __restrict__ ajb)
{
    __shared__ float Wt[IN_CH * IN_CH];
    __shared__ float bsh[IN_CH], ais[IN_CH], ajs[IN_CH];
    int tid = threadIdx.x;
    for (int i = tid; i < IN_CH * IN_CH; i += 256) {
        int c = i >> 6, k = i & 63;
        Wt[k * IN_CH + c] = W[i];
    }
    if (tid < IN_CH) { bsh[tid] = b[tid]; ais[tid] = aiw[tid]; ajs[tid] = ajw[tid]; }
    __syncthreads();

    int lane = tid & 31;
    int n = blockIdx.x * 8 + (tid >> 5);
    if (n >= N_NODES) return;

    float iv0 = in[(size_t)n * IN_CH + lane];
    float iv1 = in[(size_t)n * IN_CH + 32 + lane];
    float acc0 = bsh[lane], acc1 = bsh[32 + lane];
#pragma unroll
    for (int k = 0; k < 32; k++) {
        float v = __shfl_sync(0xffffffffu, iv0, k);
        acc0 += v * Wt[k * IN_CH + lane];
        acc1 += v * Wt[k * IN_CH + 32 + lane];
    }
#pragma unroll
    for (int k = 0; k < 32; k++) {
        float v = __shfl_sync(0xffffffffu, iv1, k);
        acc0 += v * Wt[(k + 32) * IN_CH + lane];
        acc1 += v * Wt[(k + 32) * IN_CH + 32 + lane];
    }
    g_x[(size_t)n * IN_CH + lane]      = acc0;
    g_x[(size_t)n * IN_CH + 32 + lane] = acc1;

    float ap = acc0 * ais[lane] + acc1 * ais[32 + lane];
    float jp = acc0 * ajs[lane] + acc1 * ajs[32 + lane];
#pragma unroll
    for (int o = 16; o > 0; o >>= 1) {
        ap += __shfl_xor_sync(0xffffffffu, ap, o);
        jp += __shfl_xor_sync(0xffffffffu, jp, o);
    }
    if (lane == 0) { g_ai[n] = ap + aib[0]; g_aj[n] = jp + ajb[0]; }
}

__global__ void k_zero_seg()
{
    int i = blockIdx.x * blockDim.x + threadIdx.x;
    if (i < N_NODES) { g_mkey[i] = 0u; g_ssum[i] = 0.0f; }
}

// ---- alpha + segment max over src -----------------------------------------------
__global__ void k_alpha_max(const int* __restrict__ src, const int* __restrict__ dst,
                            const float* __restrict__ ew)
{
    int i = blockIdx.x * blockDim.x + threadIdx.x;
    if (i >= N_EDGES) return;
    int s = src[i], d = dst[i];
    float a = g_ai[d] + g_aj[s] + ew[i];
    a = a > 0.0f ? a : NEG_SLOPE * a;
    g_alpha[i] = a;
    atomicMax(&g_mkey[s], fkey(a));
}

// ---- ex = exp(alpha - m[src]); segment sum over src -----------------------------
__global__ void k_exp_sum(const int* __restrict__ src)
{
    int i = blockIdx.x * blockDim.x + threadIdx.x;
    if (i >= N_EDGES) return;
    int s = src[i];
    float m = funkey(g_mkey[s]);
    float ex = __expf(g_alpha[i] - m);
    g_alpha[i] = ex;
    atomicAdd(&g_ssum[s], ex);
}

// ---- gather-aggregate per dst node (warp per node, no atomics) ------------------
// out[d] = relu( sum coef*x[src] + (sum coef*r_e)@relW^T + (sum coef)*relB )
__global__ void k_gather(const int* __restrict__ src,
                         const float* __restrict__ r,
                         const float* __restrict__ relW,   // [64,32]
                         const float* __restrict__ relB,
                         float* __restrict__ out)
{
    __shared__ float Ws[REL_DIM * IN_CH];  // Ws[k*64+c] = relW[c*32+k]
    __shared__ float Bs[IN_CH];
    int tid = threadIdx.x;
    for (int i = tid; i < REL_DIM * IN_CH; i += 256) {
        int c = i >> 5, k = i & 31;
        Ws[k * IN_CH + c] = relW[i];
    }
    if (tid < IN_CH) Bs[tid] = relB[tid];
    __syncthreads();

    int lane = tid & 31;
    int node = blockIdx.x * 8 + (tid >> 5);
    if (node >= N_NODES) return;

    int start = g_rowst[node];
    int deg   = g_deg[node];

    float acc0 = 0.f, acc1 = 0.f, accr = 0.f, csum = 0.f;

    for (int base = 0; base < deg; base += 32) {
        int m = deg - base; if (m > 32) m = 32;
        int eid = 0, s = 0; float cf = 0.f;
        if (lane < m) {
            eid = g_perm[start + base + lane];
            s   = src[eid];
            cf  = g_alpha[eid] / (g_ssum[s] + 1e-16f);
        }
        csum += cf;
#pragma unroll 4
        for (int j = 0; j < m; j++) {
            float cj = __shfl_sync(0xffffffffu, cf,  j);
            int   sj = __shfl_sync(0xffffffffu, s,   j);
            int   ej = __shfl_sync(0xffffffffu, eid, j);
            acc0 += cj * g_x[(size_t)sj * IN_CH + lane];
            acc1 += cj * g_x[(size_t)sj * IN_CH + 32 + lane];
            accr += cj * r[(size_t)ej * REL_DIM + lane];
        }
    }

#pragma unroll
    for (int o = 16; o > 0; o >>= 1)
        csum += __shfl_xor_sync(0xffffffffu, csum, o);

    float o0 = 0.f, o1 = 0.f;
#pragma unroll
    for (int k = 0; k < REL_DIM; k++) {
        float v = __shfl_sync(0xffffffffu, accr, k);
        o0 += v * Ws[k * IN_CH + lane];
        o1 += v * Ws[k * IN_CH + 32 + lane];
    }

    float r0 = acc0 + o0 + csum * Bs[lane];
    float r1 = acc1 + o1 + csum * Bs[32 + lane];
    out[(size_t)node * IN_CH + lane]      = fmaxf(r0, 0.f);
    out[(size_t)node * IN_CH + 32 + lane] = fmaxf(r1, 0.f);
}

extern "C" void kernel_launch(void* const* d_in, const int* in_sizes, int n_in,
                              void* d_out, int out_size)
{
    const float* feat   = (const float*)d_in[0];
    const int*   eidx   = (const int*)  d_in[1];
    const float* r      = (const float*)d_in[2];
    const float* rel_w  = (const float*)d_in[3];
    const float* rel_b  = (const float*)d_in[4];
    const float* c1_lw  = (const float*)d_in[5];
    const float* c1_lb  = (const float*)d_in[6];
    const float* c1_aiw = (const float*)d_in[7];
    const float* c1_aib = (const float*)d_in[8];
    const float* c1_ajw = (const float*)d_in[9];
    const float* c1_ajb = (const float*)d_in[10];
    const float* c1_eww = (const float*)d_in[11];
    const float* c1_ewb = (const float*)d_in[12];
    const float* c2_lw  = (const float*)d_in[13];
    const float* c2_lb  = (const float*)d_in[14];
    const float* c2_aiw = (const float*)d_in[15];
    const float* c2_aib = (const float*)d_in[16];
    const float* c2_ajw = (const float*)d_in[17];
    const float* c2_ajb = (const float*)d_in[18];
    const float* c2_eww = (const float*)d_in[19];
    const float* c2_ewb = (const float*)d_in[20];
    float* out = (float*)d_out;

    const int* src = eidx;
    const int* dst = eidx + N_EDGES;

    float* g_h_ptr;  cudaGetSymbolAddress((void**)&g_h_ptr, g_h);
    const float* ew1p; cudaGetSymbolAddress((void**)&ew1p, g_ew1);
    const float* ew2p; cudaGetSymbolAddress((void**)&ew2p, g_ew2);

    const int ET = (N_EDGES + 255) / 256;
    const int NB = (N_NODES + 7) / 8;
    const int NT = (N_NODES + 255) / 256;

    // edge scalar precompute (single pass over r) + CSR build (reused by both layers)
    k_ewvec<<<1, 64>>>(rel_w, rel_b, c1_eww, c1_ewb, c2_eww, c2_ewb);
    k_ew<<<ET, 256>>>(r);
    k_zero_deg<<<NT, 256>>>();
    k_hist<<<ET, 256>>>(dst);
    k_scan<<<1, 1024>>>();
    k_scatter<<<ET, 256>>>(dst);

    // ---- layer 1 ----
    k_node_transform<<<NB, 256>>>(feat, c1_lw, c1_lb, c1_aiw, c1_aib, c1_ajw, c1_ajb);
    k_zero_seg<<<NT, 256>>>();
    k_alpha_max<<<ET, 256>>>(src, dst, ew1p);
    k_exp_sum<<<ET, 256>>>(src);
    k_gather<<<NB, 256>>>(src, r, rel_w, rel_b, g_h_ptr);

    // ---- layer 2 ----
    k_node_transform<<<NB, 256>>>(g_h_ptr, c2_lw, c2_lb, c2_aiw, c2_aib, c2_ajw, c2_ajb);
    k_zero_seg<<<NT, 256>>>();
    k_alpha_max<<<ET, 256>>>(src, dst, ew2p);
    k_exp_sum<<<ET, 256>>>(src);
    k_gather<<<NB, 256>>>(src, r, rel_w, rel_b, out);
}

// round 5
// speedup vs baseline: 2.6633x; 1.0850x over previous
#include <cuda_runtime.h>
#include <cuda_bf16.h>

#define N_NODES 50000
#define IN_CH   64
#define REL_DIM 32
#define N_EDGES 800000
#define NEG_SLOPE 0.01f

// ---------------- scratch (device globals) ----------------
__device__ float    g_ew1  [N_EDGES];
__device__ float    g_ew2  [N_EDGES];
__device__ float    g_alpha[N_EDGES];          // alpha, then ex
__device__ float    g_x    [N_NODES * IN_CH];
__device__ float    g_h    [N_NODES * IN_CH];
__device__ float    g_ai   [N_NODES];
__device__ float    g_aj   [N_NODES];
__device__ unsigned g_mkey1[N_NODES];
__device__ float    g_ssum1[N_NODES];
__device__ unsigned g_mkey2[N_NODES];
__device__ float    g_ssum2[N_NODES];
__device__ int      g_deg  [N_NODES];
__device__ int      g_rowst[N_NODES];
__device__ int      g_curs [N_NODES];
__device__ int2     g_edge [N_EDGES];          // {src, eid} in dst-CSR order
__device__ float    g_v1   [REL_DIM];
__device__ float    g_v2   [REL_DIM];
__device__ float    g_ewc  [2];

__device__ __forceinline__ unsigned fkey(float f) {
    unsigned b = __float_as_uint(f);
    return (b & 0x80000000u) ? ~b : (b | 0x80000000u);
}
__device__ __forceinline__ float funkey(unsigned u) {
    unsigned b = (u & 0x80000000u) ? (u & 0x7fffffffu) : ~u;
    return __uint_as_float(b);
}

// ---- init: zero deg + both layers' softmax accumulators -------------------------
__global__ void k_init()
{
    int i = blockIdx.x * blockDim.x + threadIdx.x;
    if (i < N_NODES) {
        g_deg[i] = 0;
        g_mkey1[i] = 0u; g_ssum1[i] = 0.0f;
        g_mkey2[i] = 0u; g_ssum2[i] = 0.0f;
    }
}

// ---- fold ew linear through rel linear: v = relW^T @ ew_w ; c = relB.ew_w + ew_b
__global__ void k_ewvec(const float* __restrict__ relW, const float* __restrict__ relB,
                        const float* __restrict__ w1, const float* __restrict__ b1,
                        const float* __restrict__ w2, const float* __restrict__ b2)
{
    int t = threadIdx.x;
    if (t < REL_DIM) {
        float a1 = 0.f, a2 = 0.f;
#pragma unroll
        for (int c = 0; c < IN_CH; c++) {
            float w = relW[c * REL_DIM + t];
            a1 += w * w1[c];
            a2 += w * w2[c];
        }
        g_v1[t] = a1; g_v2[t] = a2;
    } else if (t == 32) {
        float s = 0.f;
        for (int c = 0; c < IN_CH; c++) s += relB[c] * w1[c];
        g_ewc[0] = s + b1[0];
    } else if (t == 33) {
        float s = 0.f;
        for (int c = 0; c < IN_CH; c++) s += relB[c] * w2[c];
        g_ewc[1] = s + b2[0];
    }
}

// ---- ew1/ew2 per edge (stream r) + dst histogram --------------------------------
__global__ void k_ew_hist(const float* __restrict__ r, const int* __restrict__ dst)
{
    __shared__ float sv1[REL_DIM], sv2[REL_DIM], sc[2];
    int t = threadIdx.x;
    if (t < REL_DIM) { sv1[t] = g_v1[t]; sv2[t] = g_v2[t]; }
    if (t < 2) sc[t] = g_ewc[t];
    __syncthreads();
    int e = blockIdx.x * 256 + t;
    if (e >= N_EDGES) return;
    const float4* rp = reinterpret_cast<const float4*>(r + (size_t)e * REL_DIM);
    float a1 = 0.f, a2 = 0.f;
#pragma unroll
    for (int q = 0; q < 8; q++) {
        float4 f = rp[q];
        a1 += f.x * sv1[4*q] + f.y * sv1[4*q+1] + f.z * sv1[4*q+2] + f.w * sv1[4*q+3];
        a2 += f.x * sv2[4*q] + f.y * sv2[4*q+1] + f.z * sv2[4*q+2] + f.w * sv2[4*q+3];
    }
    g_ew1[e] = a1 + sc[0];
    g_ew2[e] = a2 + sc[1];
    atomicAdd(&g_deg[dst[e]], 1);
}

// ---- exclusive scan of deg -> rowst, curs ---------------------------------------
__global__ void k_scan()
{
    __shared__ int wsum[32];
    __shared__ int carry_s;
    int t = threadIdx.x, lane = t & 31, wid = t >> 5;
    if (t == 0) carry_s = 0;
    __syncthreads();
    for (int base = 0; base < N_NODES; base += 1024) {
        int i = base + t;
        int v = (i < N_NODES) ? g_deg[i] : 0;
        int x = v;
#pragma unroll
        for (int off = 1; off < 32; off <<= 1) {
            int y = __shfl_up_sync(0xffffffffu, x, off);
            if (lane >= off) x += y;
        }
        if (lane == 31) wsum[wid] = x;
        __syncthreads();
        if (wid == 0) {
            int s = wsum[lane];
#pragma unroll
            for (int off = 1; off < 32; off <<= 1) {
                int y = __shfl_up_sync(0xffffffffu, s, off);
                if (lane >= off) s += y;
            }
            wsum[lane] = s;
        }
        __syncthreads();
        int warpoff = (wid == 0) ? 0 : wsum[wid - 1];
        int excl = carry_s + warpoff + x - v;
        if (i < N_NODES) { g_rowst[i] = excl; g_curs[i] = excl; }
        __syncthreads();
        if (t == 0) carry_s += wsum[31];
        __syncthreads();
    }
}

// ---- scatter packed {src, eid} records into dst-CSR order -----------------------
__global__ void k_scatter(const int* __restrict__ src, const int* __restrict__ dst)
{
    int i = blockIdx.x * blockDim.x + threadIdx.x;
    if (i >= N_EDGES) return;
    int p = atomicAdd(&g_curs[dst[i]], 1);
    g_edge[p] = make_int2(src[i], i);
}

// ---- node transform + per-node attention scalars (warp per node) ----------------
__global__ void k_node_transform(const float* __restrict__ in,
                                 const float* __restrict__ W,
                                 const float* __restrict__ b,
                                 const float* __restrict__ aiw, const float* __restrict__ aib,
                                 const float* __restrict__ ajw, const float* __restrict__ ajb)
{
    __shared__ float Wt[IN_CH * IN_CH];
    __shared__ float bsh[IN_CH], ais[IN_CH], ajs[IN_CH];
    int tid = threadIdx.x;
    for (int i = tid; i < IN_CH * IN_CH; i += 256) {
        int c = i >> 6, k = i & 63;
        Wt[k * IN_CH + c] = W[i];
    }
    if (tid < IN_CH) { bsh[tid] = b[tid]; ais[tid] = aiw[tid]; ajs[tid] = ajw[tid]; }
    __syncthreads();

    int lane = tid & 31;
    int n = blockIdx.x * 8 + (tid >> 5);
    if (n >= N_NODES) return;

    float iv0 = in[(size_t)n * IN_CH + lane];
    float iv1 = in[(size_t)n * IN_CH + 32 + lane];
    float acc0 = bsh[lane], acc1 = bsh[32 + lane];
#pragma unroll
    for (int k = 0; k < 32; k++) {
        float v = __shfl_sync(0xffffffffu, iv0, k);
        acc0 += v * Wt[k * IN_CH + lane];
        acc1 += v * Wt[k * IN_CH + 32 + lane];
    }
#pragma unroll
    for (int k = 0; k < 32; k++) {
        float v = __shfl_sync(0xffffffffu, iv1, k);
        acc0 += v * Wt[(k + 32) * IN_CH + lane];
        acc1 += v * Wt[(k + 32) * IN_CH + 32 + lane];
    }
    g_x[(size_t)n * IN_CH + lane]      = acc0;
    g_x[(size_t)n * IN_CH + 32 + lane] = acc1;

    float ap = acc0 * ais[lane] + acc1 * ais[32 + lane];
    float jp = acc0 * ajs[lane] + acc1 * ajs[32 + lane];
#pragma unroll
    for (int o = 16; o > 0; o >>= 1) {
        ap += __shfl_xor_sync(0xffffffffu, ap, o);
        jp += __shfl_xor_sync(0xffffffffu, jp, o);
    }
    if (lane == 0) { g_ai[n] = ap + aib[0]; g_aj[n] = jp + ajb[0]; }
}

// ---- alpha + segment max over src -----------------------------------------------
__global__ void k_alpha_max(const int* __restrict__ src, const int* __restrict__ dst,
                            const float* __restrict__ ew, unsigned* __restrict__ mkey)
{
    int i = blockIdx.x * blockDim.x + threadIdx.x;
    if (i >= N_EDGES) return;
    int s = src[i], d = dst[i];
    float a = g_ai[d] + g_aj[s] + ew[i];
    a = a > 0.0f ? a : NEG_SLOPE * a;
    g_alpha[i] = a;
    atomicMax(&mkey[s], fkey(a));
}

// ---- ex = exp(alpha - m[src]); segment sum over src -----------------------------
__global__ void k_exp_sum(const int* __restrict__ src,
                          const unsigned* __restrict__ mkey, float* __restrict__ ssum)
{
    int i = blockIdx.x * blockDim.x + threadIdx.x;
    if (i >= N_EDGES) return;
    int s = src[i];
    float m = funkey(mkey[s]);
    float ex = __expf(g_alpha[i] - m);
    g_alpha[i] = ex;
    atomicAdd(&ssum[s], ex);
}

// ---- gather-aggregate per dst node (warp per node, no atomics) ------------------
// out[d] = relu( sum coef*x[src] + (sum coef*r_e)@relW^T + (sum coef)*relB )
__global__ void __launch_bounds__(256)
k_gather(const float* __restrict__ r,
         const float* __restrict__ relW,   // [64,32]
         const float* __restrict__ relB,
         const float* __restrict__ ssum,
         float* __restrict__ out)
{
    __shared__ float Ws[REL_DIM * IN_CH];  // Ws[k*64+c] = relW[c*32+k]
    __shared__ float Bs[IN_CH];
    int tid = threadIdx.x;
    for (int i = tid; i < REL_DIM * IN_CH; i += 256) {
        int c = i >> 5, k = i & 31;
        Ws[k * IN_CH + c] = relW[i];
    }
    if (tid < IN_CH) Bs[tid] = relB[tid];
    __syncthreads();

    int lane = tid & 31;
    int node = blockIdx.x * 8 + (tid >> 5);
    if (node >= N_NODES) return;

    int start = g_rowst[node];
    int deg   = g_deg[node];

    float acc0 = 0.f, acc1 = 0.f, accr = 0.f, csum = 0.f;

    int base = 0;
    // full chunks: fixed trip count -> deep unroll / MLP
    for (; base + 32 <= deg; base += 32) {
        int2 se = g_edge[start + base + lane];
        float cf = g_alpha[se.y] / (ssum[se.x] + 1e-16f);
        csum += cf;
#pragma unroll 8
        for (int j = 0; j < 32; j++) {
            float cj = __shfl_sync(0xffffffffu, cf,   j);
            int   sj = __shfl_sync(0xffffffffu, se.x, j);
            int   ej = __shfl_sync(0xffffffffu, se.y, j);
            acc0 += cj * g_x[(size_t)sj * IN_CH + lane];
            acc1 += cj * g_x[(size_t)sj * IN_CH + 32 + lane];
            accr += cj * r[(size_t)ej * REL_DIM + lane];
        }
    }
    int m = deg - base;
    if (m > 0) {
        int2 se = make_int2(0, 0);
        float cf = 0.f;
        if (lane < m) {
            se = g_edge[start + base + lane];
            cf = g_alpha[se.y] / (ssum[se.x] + 1e-16f);
        }
        csum += cf;
#pragma unroll 4
        for (int j = 0; j < 32; j++) {
            if (j >= m) break;
            float cj = __shfl_sync(0xffffffffu, cf,   j);
            int   sj = __shfl_sync(0xffffffffu, se.x, j);
            int   ej = __shfl_sync(0xffffffffu, se.y, j);
            acc0 += cj * g_x[(size_t)sj * IN_CH + lane];
            acc1 += cj * g_x[(size_t)sj * IN_CH + 32 + lane];
            accr += cj * r[(size_t)ej * REL_DIM + lane];
        }
    }

#pragma unroll
    for (int o = 16; o > 0; o >>= 1)
        csum += __shfl_xor_sync(0xffffffffu, csum, o);

    float o0 = 0.f, o1 = 0.f;
#pragma unroll
    for (int k = 0; k < REL_DIM; k++) {
        float v = __shfl_sync(0xffffffffu, accr, k);
        o0 += v * Ws[k * IN_CH + lane];
        o1 += v * Ws[k * IN_CH + 32 + lane];
    }

    float r0 = acc0 + o0 + csum * Bs[lane];
    float r1 = acc1 + o1 + csum * Bs[32 + lane];
    out[(size_t)node * IN_CH + lane]      = fmaxf(r0, 0.f);
    out[(size_t)node * IN_CH + 32 + lane] = fmaxf(r1, 0.f);
}

extern "C" void kernel_launch(void* const* d_in, const int* in_sizes, int n_in,
                              void* d_out, int out_size)
{
    const float* feat   = (const float*)d_in[0];
    const int*   eidx   = (const int*)  d_in[1];
    const float* r      = (const float*)d_in[2];
    const float* rel_w  = (const float*)d_in[3];
    const float* rel_b  = (const float*)d_in[4];
    const float* c1_lw  = (const float*)d_in[5];
    const float* c1_lb  = (const float*)d_in[6];
    const float* c1_aiw = (const float*)d_in[7];
    const float* c1_aib = (const float*)d_in[8];
    const float* c1_ajw = (const float*)d_in[9];
    const float* c1_ajb = (const float*)d_in[10];
    const float* c1_eww = (const float*)d_in[11];
    const float* c1_ewb = (const float*)d_in[12];
    const float* c2_lw  = (const float*)d_in[13];
    const float* c2_lb  = (const float*)d_in[14];
    const float* c2_aiw = (const float*)d_in[15];
    const float* c2_aib = (const float*)d_in[16];
    const float* c2_ajw = (const float*)d_in[17];
    const float* c2_ajb = (const float*)d_in[18];
    const float* c2_eww = (const float*)d_in[19];
    const float* c2_ewb = (const float*)d_in[20];
    float* out = (float*)d_out;

    const int* src = eidx;
    const int* dst = eidx + N_EDGES;

    float* g_h_ptr;  cudaGetSymbolAddress((void**)&g_h_ptr, g_h);
    const float* ew1p; cudaGetSymbolAddress((void**)&ew1p, g_ew1);
    const float* ew2p; cudaGetSymbolAddress((void**)&ew2p, g_ew2);
    unsigned* mk1; cudaGetSymbolAddress((void**)&mk1, g_mkey1);
    unsigned* mk2; cudaGetSymbolAddress((void**)&mk2, g_mkey2);
    float* ss1; cudaGetSymbolAddress((void**)&ss1, g_ssum1);
    float* ss2; cudaGetSymbolAddress((void**)&ss2, g_ssum2);

    const int ET = (N_EDGES + 255) / 256;
    const int NB = (N_NODES + 7) / 8;
    const int NT = (N_NODES + 255) / 256;

    // shared precompute: init, folded ew vectors, ew scalars + hist, CSR build
    k_init<<<NT, 256>>>();
    k_ewvec<<<1, 64>>>(rel_w, rel_b, c1_eww, c1_ewb, c2_eww, c2_ewb);
    k_ew_hist<<<ET, 256>>>(r, dst);
    k_scan<<<1, 1024>>>();
    k_scatter<<<ET, 256>>>(src, dst);

    // ---- layer 1 ----
    k_node_transform<<<NB, 256>>>(feat, c1_lw, c1_lb, c1_aiw, c1_aib, c1_ajw, c1_ajb);
    k_alpha_max<<<ET, 256>>>(src, dst, ew1p, mk1);
    k_exp_sum<<<ET, 256>>>(src, mk1, ss1);
    k_gather<<<NB, 256>>>(r, rel_w, rel_b, ss1, g_h_ptr);

    // ---- layer 2 ----
    k_node_transform<<<NB, 256>>>(g_h_ptr, c2_lw, c2_lb, c2_aiw, c2_aib, c2_ajw, c2_ajb);
    k_alpha_max<<<ET, 256>>>(src, dst, ew2p, mk2);
    k_exp_sum<<<ET, 256>>>(src, mk2, ss2);
    k_gather<<<NB, 256>>>(r, rel_w, rel_b, ss2, out);
}

// round 6
// speedup vs baseline: 2.6749x; 1.0044x over previous
#include <cuda_runtime.h>
#include <cuda_bf16.h>

#define N_NODES 50000
#define IN_CH   64
#define REL_DIM 32
#define N_EDGES 800000
#define NEG_SLOPE 0.01f

#define SCAN_BLK 512
#define SCAN_NB  ((N_NODES + SCAN_BLK - 1) / SCAN_BLK)   // 98

// ---------------- scratch (device globals) ----------------
__device__ float    g_ew1  [N_EDGES];
__device__ float    g_ew2  [N_EDGES];
__device__ float    g_alpha[N_EDGES];          // alpha, then ex
__device__ float    g_x    [N_NODES * IN_CH];
__device__ float    g_h    [N_NODES * IN_CH];
__device__ float    g_ai   [N_NODES];
__device__ float    g_aj   [N_NODES];
__device__ unsigned g_mkey1[N_NODES];
__device__ float    g_ssum1[N_NODES];
__device__ unsigned g_mkey2[N_NODES];
__device__ float    g_ssum2[N_NODES];
__device__ int      g_deg  [N_NODES];
__device__ int      g_rowst[N_NODES];
__device__ int      g_curs [N_NODES];
__device__ int      g_bsum [SCAN_NB];
__device__ int      g_boff [SCAN_NB];
__device__ int2     g_edge [N_EDGES];          // {src, eid} in dst-CSR order
__device__ float    g_v1   [REL_DIM];
__device__ float    g_v2   [REL_DIM];
__device__ float    g_ewc  [2];

__device__ __forceinline__ unsigned fkey(float f) {
    unsigned b = __float_as_uint(f);
    return (b & 0x80000000u) ? ~b : (b | 0x80000000u);
}
__device__ __forceinline__ float funkey(unsigned u) {
    unsigned b = (u & 0x80000000u) ? (u & 0x7fffffffu) : ~u;
    return __uint_as_float(b);
}

// ---- init: zero deg + both layers' softmax accumulators -------------------------
__global__ void k_init()
{
    int i = blockIdx.x * blockDim.x + threadIdx.x;
    if (i < N_NODES) {
        g_deg[i] = 0;
        g_mkey1[i] = 0u; g_ssum1[i] = 0.0f;
        g_mkey2[i] = 0u; g_ssum2[i] = 0.0f;
    }
}

// ---- fold ew linear through rel linear ------------------------------------------
__global__ void k_ewvec(const float* __restrict__ relW, const float* __restrict__ relB,
                        const float* __restrict__ w1, const float* __restrict__ b1,
                        const float* __restrict__ w2, const float* __restrict__ b2)
{
    int t = threadIdx.x;
    if (t < REL_DIM) {
        float a1 = 0.f, a2 = 0.f;
#pragma unroll
        for (int c = 0; c < IN_CH; c++) {
            float w = relW[c * REL_DIM + t];
            a1 += w * w1[c];
            a2 += w * w2[c];
        }
        g_v1[t] = a1; g_v2[t] = a2;
    } else if (t == 32) {
        float s = 0.f;
        for (int c = 0; c < IN_CH; c++) s += relB[c] * w1[c];
        g_ewc[0] = s + b1[0];
    } else if (t == 33) {
        float s = 0.f;
        for (int c = 0; c < IN_CH; c++) s += relB[c] * w2[c];
        g_ewc[1] = s + b2[0];
    }
}

// ---- ew1/ew2 per edge (stream r) + dst histogram --------------------------------
__global__ void k_ew_hist(const float* __restrict__ r, const int* __restrict__ dst)
{
    __shared__ float sv1[REL_DIM], sv2[REL_DIM], sc[2];
    int t = threadIdx.x;
    if (t < REL_DIM) { sv1[t] = g_v1[t]; sv2[t] = g_v2[t]; }
    if (t < 2) sc[t] = g_ewc[t];
    __syncthreads();
    int e = blockIdx.x * 256 + t;
    if (e >= N_EDGES) return;
    const float4* rp = reinterpret_cast<const float4*>(r + (size_t)e * REL_DIM);
    float a1 = 0.f, a2 = 0.f;
#pragma unroll
    for (int q = 0; q < 8; q++) {
        float4 f = rp[q];
        a1 += f.x * sv1[4*q] + f.y * sv1[4*q+1] + f.z * sv1[4*q+2] + f.w * sv1[4*q+3];
        a2 += f.x * sv2[4*q] + f.y * sv2[4*q+1] + f.z * sv2[4*q+2] + f.w * sv2[4*q+3];
    }
    g_ew1[e] = a1 + sc[0];
    g_ew2[e] = a2 + sc[1];
    atomicAdd(&g_deg[dst[e]], 1);
}

// ---- multi-block exclusive scan of deg ------------------------------------------
// phase 1: block-local exclusive scan (512/block), block totals to g_bsum
__global__ void __launch_bounds__(SCAN_BLK) k_scan1()
{
    __shared__ int wsum[SCAN_BLK / 32];
    int t = threadIdx.x, lane = t & 31, wid = t >> 5;
    int i = blockIdx.x * SCAN_BLK + t;
    int v = (i < N_NODES) ? g_deg[i] : 0;
    int x = v;
#pragma unroll
    for (int off = 1; off < 32; off <<= 1) {
        int y = __shfl_up_sync(0xffffffffu, x, off);
        if (lane >= off) x += y;
    }
    if (lane == 31) wsum[wid] = x;
    __syncthreads();
    if (wid == 0) {
        int s = (lane < SCAN_BLK / 32) ? wsum[lane] : 0;
#pragma unroll
        for (int off = 1; off < SCAN_BLK / 32; off <<= 1) {
            int y = __shfl_up_sync(0xffffffffu, s, off);
            if (lane >= off) s += y;
        }
        if (lane < SCAN_BLK / 32) wsum[lane] = s;
    }
    __syncthreads();
    int woff = (wid == 0) ? 0 : wsum[wid - 1];
    if (i < N_NODES) g_rowst[i] = woff + x - v;   // block-local exclusive
    if (t == SCAN_BLK - 1) g_bsum[blockIdx.x] = woff + x;
}

// phase 2: exclusive scan of SCAN_NB block totals (single 128-thread block)
__global__ void k_scan2()
{
    __shared__ int wsum[4];
    int t = threadIdx.x, lane = t & 31, wid = t >> 5;
    int v = (t < SCAN_NB) ? g_bsum[t] : 0;
    int x = v;
#pragma unroll
    for (int off = 1; off < 32; off <<= 1) {
        int y = __shfl_up_sync(0xffffffffu, x, off);
        if (lane >= off) x += y;
    }
    if (lane == 31) wsum[wid] = x;
    __syncthreads();
    if (wid == 0 && lane < 4) {
        int s = wsum[lane];
#pragma unroll
        for (int off = 1; off < 4; off <<= 1) {
            int y = __shfl_up_sync(0x0000000fu, s, off);
            if (lane >= off) s += y;
        }
        wsum[lane] = s;
    }
    __syncthreads();
    int woff = (wid == 0) ? 0 : wsum[wid - 1];
    if (t < SCAN_NB) g_boff[t] = woff + x - v;
}

// phase 3: add block offsets, write rowst + curs
__global__ void __launch_bounds__(SCAN_BLK) k_scan3()
{
    int i = blockIdx.x * SCAN_BLK + threadIdx.x;
    if (i >= N_NODES) return;
    int v = g_rowst[i] + g_boff[blockIdx.x];
    g_rowst[i] = v;
    g_curs[i]  = v;
}

// ---- scatter packed {src, eid} records into dst-CSR order -----------------------
__global__ void k_scatter(const int* __restrict__ src, const int* __restrict__ dst)
{
    int i = blockIdx.x * blockDim.x + threadIdx.x;
    if (i >= N_EDGES) return;
    int p = atomicAdd(&g_curs[dst[i]], 1);
    g_edge[p] = make_int2(src[i], i);
}

// ---- node transform + per-node attention scalars (warp per node) ----------------
__global__ void k_node_transform(const float* __restrict__ in,
                                 const float* __restrict__ W,
                                 const float* __restrict__ b,
                                 const float* __restrict__ aiw, const float* __restrict__ aib,
                                 const float* __restrict__ ajw, const float* __restrict__ ajb)
{
    __shared__ float Wt[IN_CH * IN_CH];
    __shared__ float bsh[IN_CH], ais[IN_CH], ajs[IN_CH];
    int tid = threadIdx.x;
    for (int i = tid; i < IN_CH * IN_CH; i += 256) {
        int c = i >> 6, k = i & 63;
        Wt[k * IN_CH + c] = W[i];
    }
    if (tid < IN_CH) { bsh[tid] = b[tid]; ais[tid] = aiw[tid]; ajs[tid] = ajw[tid]; }
    __syncthreads();

    int lane = tid & 31;
    int n = blockIdx.x * 8 + (tid >> 5);
    if (n >= N_NODES) return;

    float iv0 = in[(size_t)n * IN_CH + lane];
    float iv1 = in[(size_t)n * IN_CH + 32 + lane];
    float acc0 = bsh[lane], acc1 = bsh[32 + lane];
#pragma unroll
    for (int k = 0; k < 32; k++) {
        float v = __shfl_sync(0xffffffffu, iv0, k);
        acc0 += v * Wt[k * IN_CH + lane];
        acc1 += v * Wt[k * IN_CH + 32 + lane];
    }
#pragma unroll
    for (int k = 0; k < 32; k++) {
        float v = __shfl_sync(0xffffffffu, iv1, k);
        acc0 += v * Wt[(k + 32) * IN_CH + lane];
        acc1 += v * Wt[(k + 32) * IN_CH + 32 + lane];
    }
    g_x[(size_t)n * IN_CH + lane]      = acc0;
    g_x[(size_t)n * IN_CH + 32 + lane] = acc1;

    float ap = acc0 * ais[lane] + acc1 * ais[32 + lane];
    float jp = acc0 * ajs[lane] + acc1 * ajs[32 + lane];
#pragma unroll
    for (int o = 16; o > 0; o >>= 1) {
        ap += __shfl_xor_sync(0xffffffffu, ap, o);
        jp += __shfl_xor_sync(0xffffffffu, jp, o);
    }
    if (lane == 0) { g_ai[n] = ap + aib[0]; g_aj[n] = jp + ajb[0]; }
}

// ---- alpha + segment max over src -----------------------------------------------
__global__ void k_alpha_max(const int* __restrict__ src, const int* __restrict__ dst,
                            const float* __restrict__ ew, unsigned* __restrict__ mkey)
{
    int i = blockIdx.x * blockDim.x + threadIdx.x;
    if (i >= N_EDGES) return;
    int s = src[i], d = dst[i];
    float a = g_ai[d] + g_aj[s] + ew[i];
    a = a > 0.0f ? a : NEG_SLOPE * a;
    g_alpha[i] = a;
    atomicMax(&mkey[s], fkey(a));
}

// ---- ex = exp(alpha - m[src]); segment sum over src -----------------------------
__global__ void k_exp_sum(const int* __restrict__ src,
                          const unsigned* __restrict__ mkey, float* __restrict__ ssum)
{
    int i = blockIdx.x * blockDim.x + threadIdx.x;
    if (i >= N_EDGES) return;
    int s = src[i];
    float m = funkey(mkey[s]);
    float ex = __expf(g_alpha[i] - m);
    g_alpha[i] = ex;
    atomicAdd(&ssum[s], ex);
}

// ---- gather-aggregate per dst node (warp per node, no atomics) ------------------
__global__ void __launch_bounds__(256)
k_gather(const float* __restrict__ r,
         const float* __restrict__ relW,   // [64,32]
         const float* __restrict__ relB,
         const float* __restrict__ ssum,
         float* __restrict__ out)
{
    __shared__ float Ws[REL_DIM * IN_CH];  // Ws[k*64+c] = relW[c*32+k]
    __shared__ float Bs[IN_CH];
    int tid = threadIdx.x;
    for (int i = tid; i < REL_DIM * IN_CH; i += 256) {
        int c = i >> 5, k = i & 31;
        Ws[k * IN_CH + c] = relW[i];
    }
    if (tid < IN_CH) Bs[tid] = relB[tid];
    __syncthreads();

    int lane = tid & 31;
    int node = blockIdx.x * 8 + (tid >> 5);
    if (node >= N_NODES) return;

    int start = g_rowst[node];
    int deg   = g_deg[node];

    float acc0 = 0.f, acc1 = 0.f, accr = 0.f, csum = 0.f;

    int base = 0;
    // full chunks: fixed trip count -> deep unroll / MLP
    for (; base + 32 <= deg; base += 32) {
        int2 se = g_edge[start + base + lane];
        float cf = g_alpha[se.y] / (ssum[se.x] + 1e-16f);
        csum += cf;
#pragma unroll 8
        for (int j = 0; j < 32; j++) {
            float cj = __shfl_sync(0xffffffffu, cf,   j);
            int   sj = __shfl_sync(0xffffffffu, se.x, j);
            int   ej = __shfl_sync(0xffffffffu, se.y, j);
            acc0 += cj * g_x[(size_t)sj * IN_CH + lane];
            acc1 += cj * g_x[(size_t)sj * IN_CH + 32 + lane];
            accr += cj * r[(size_t)ej * REL_DIM + lane];
        }
    }
    int m = deg - base;
    if (m > 0) {
        int2 se = make_int2(0, 0);
        float cf = 0.f;
        if (lane < m) {
            se = g_edge[start + base + lane];
            cf = g_alpha[se.y] / (ssum[se.x] + 1e-16f);
        }
        csum += cf;
        // warp-uniform guard, no break: lets the compiler unroll + keep loads in flight
#pragma unroll 8
        for (int j = 0; j < 32; j++) {
            if (j < m) {
                float cj = __shfl_sync(0xffffffffu, cf,   j);
                int   sj = __shfl_sync(0xffffffffu, se.x, j);
                int   ej = __shfl_sync(0xffffffffu, se.y, j);
                acc0 += cj * g_x[(size_t)sj * IN_CH + lane];
                acc1 += cj * g_x[(size_t)sj * IN_CH + 32 + lane];
                accr += cj * r[(size_t)ej * REL_DIM + lane];
            }
        }
    }

#pragma unroll
    for (int o = 16; o > 0; o >>= 1)
        csum += __shfl_xor_sync(0xffffffffu, csum, o);

    float o0 = 0.f, o1 = 0.f;
#pragma unroll
    for (int k = 0; k < REL_DIM; k++) {
        float v = __shfl_sync(0xffffffffu, accr, k);
        o0 += v * Ws[k * IN_CH + lane];
        o1 += v * Ws[k * IN_CH + 32 + lane];
    }

    float r0 = acc0 + o0 + csum * Bs[lane];
    float r1 = acc1 + o1 + csum * Bs[32 + lane];
    out[(size_t)node * IN_CH + lane]      = fmaxf(r0, 0.f);
    out[(size_t)node * IN_CH + 32 + lane] = fmaxf(r1, 0.f);
}

extern "C" void kernel_launch(void* const* d_in, const int* in_sizes, int n_in,
                              void* d_out, int out_size)
{
    const float* feat   = (const float*)d_in[0];
    const int*   eidx   = (const int*)  d_in[1];
    const float* r      = (const float*)d_in[2];
    const float* rel_w  = (const float*)d_in[3];
    const float* rel_b  = (const float*)d_in[4];
    const float* c1_lw  = (const float*)d_in[5];
    const float* c1_lb  = (const float*)d_in[6];
    const float* c1_aiw = (const float*)d_in[7];
    const float* c1_aib = (const float*)d_in[8];
    const float* c1_ajw = (const float*)d_in[9];
    const float* c1_ajb = (const float*)d_in[10];
    const float* c1_eww = (const float*)d_in[11];
    const float* c1_ewb = (const float*)d_in[12];
    const float* c2_lw  = (const float*)d_in[13];
    const float* c2_lb  = (const float*)d_in[14];
    const float* c2_aiw = (const float*)d_in[15];
    const float* c2_aib = (const float*)d_in[16];
    const float* c2_ajw = (const float*)d_in[17];
    const float* c2_ajb = (const float*)d_in[18];
    const float* c2_eww = (const float*)d_in[19];
    const float* c2_ewb = (const float*)d_in[20];
    float* out = (float*)d_out;

    const int* src = eidx;
    const int* dst = eidx + N_EDGES;

    float* g_h_ptr;  cudaGetSymbolAddress((void**)&g_h_ptr, g_h);
    const float* ew1p; cudaGetSymbolAddress((void**)&ew1p, g_ew1);
    const float* ew2p; cudaGetSymbolAddress((void**)&ew2p, g_ew2);
    unsigned* mk1; cudaGetSymbolAddress((void**)&mk1, g_mkey1);
    unsigned* mk2; cudaGetSymbolAddress((void**)&mk2, g_mkey2);
    float* ss1; cudaGetSymbolAddress((void**)&ss1, g_ssum1);
    float* ss2; cudaGetSymbolAddress((void**)&ss2, g_ssum2);

    const int ET = (N_EDGES + 255) / 256;
    const int NB = (N_NODES + 7) / 8;
    const int NT = (N_NODES + 255) / 256;

    // shared precompute
    k_init<<<NT, 256>>>();
    k_ewvec<<<1, 64>>>(rel_w, rel_b, c1_eww, c1_ewb, c2_eww, c2_ewb);
    k_ew_hist<<<ET, 256>>>(r, dst);
    k_scan1<<<SCAN_NB, SCAN_BLK>>>();
    k_scan2<<<1, 128>>>();
    k_scan3<<<SCAN_NB, SCAN_BLK>>>();
    k_scatter<<<ET, 256>>>(src, dst);

    // ---- layer 1 ----
    k_node_transform<<<NB, 256>>>(feat, c1_lw, c1_lb, c1_aiw, c1_aib, c1_ajw, c1_ajb);
    k_alpha_max<<<ET, 256>>>(src, dst, ew1p, mk1);
    k_exp_sum<<<ET, 256>>>(src, mk1, ss1);
    k_gather<<<NB, 256>>>(r, rel_w, rel_b, ss1, g_h_ptr);

    // ---- layer 2 ----
    k_node_transform<<<NB, 256>>>(g_h_ptr, c2_lw, c2_lb, c2_aiw, c2_aib, c2_ajw, c2_ajb);
    k_alpha_max<<<ET, 256>>>(src, dst, ew2p, mk2);
    k_exp_sum<<<ET, 256>>>(src, mk2, ss2);
    k_gather<<<NB, 256>>>(r, rel_w, rel_b, ss2, out);
}

// round 9
// speedup vs baseline: 3.3853x; 1.2656x over previous
#include <cuda_runtime.h>
#include <cuda_bf16.h>

#define N_NODES 50000
#define IN_CH   64
#define REL_DIM 32
#define N_EDGES 800000
#define NEG_SLOPE 0.01f

#define NBLK   592
#define NTHR   256
#define GT     (NBLK * NTHR)
#define GWARPS (NBLK * 8)
#define NCHUNK ((N_NODES + 255) / 256)   // 196
#define NBAR   12

// ---------------- scratch ----------------
__device__ float    g_ew1  [N_EDGES];
__device__ float    g_ew2  [N_EDGES];
__device__ float    g_alpha[N_EDGES];
__device__ float    g_x    [N_NODES * IN_CH];
__device__ float    g_h    [N_NODES * IN_CH];
__device__ float    g_ai   [N_NODES];
__device__ float    g_aj   [N_NODES];
__device__ unsigned g_mkey1[N_NODES];
__device__ float    g_ssum1[N_NODES];
__device__ unsigned g_mkey2[N_NODES];
__device__ float    g_ssum2[N_NODES];
__device__ int      g_deg  [N_NODES];
__device__ int      g_rowst[N_NODES];
__device__ int      g_curs [N_NODES];
__device__ int      g_bsum [NCHUNK];
__device__ int      g_boff [NCHUNK];
__device__ int2     g_edge [N_EDGES];
__device__ float    g_v1   [REL_DIM];
__device__ float    g_v2   [REL_DIM];
__device__ float    g_ewc  [2];
__device__ unsigned gA[NBAR];   // zero-initialized; self-resetting
__device__ unsigned gD[NBAR];

struct SmemXF { float Wt[IN_CH * IN_CH]; float bsh[IN_CH], ais[IN_CH], ajs[IN_CH]; };
struct SmemGT { float Ws[REL_DIM * IN_CH]; float Bs[IN_CH]; };
struct SmemEW { float sv1[REL_DIM], sv2[REL_DIM], sc[2]; };
struct SmemSC { int wsum[8]; };
union Smem { SmemXF xf; SmemGT gt; SmemEW ew; SmemSC sc; };

__device__ __forceinline__ unsigned fkey(float f) {
    unsigned b = __float_as_uint(f);
    return (b & 0x80000000u) ? ~b : (b | 0x80000000u);
}
__device__ __forceinline__ float funkey(unsigned u) {
    unsigned b = (u & 0x80000000u) ? (u & 0x7fffffffu) : ~u;
    return __uint_as_float(b);
}

// ---- software grid barrier (arrive/depart, self-resetting for replay) ----------
__device__ __forceinline__ void gsync(int id) {
    __syncthreads();
    if (threadIdx.x == 0) {
        __threadfence();
        atomicAdd(&gA[id], 1u);
        while (*((volatile unsigned*)&gA[id]) < (unsigned)NBLK) __nanosleep(64);
        unsigned d = atomicAdd(&gD[id], 1u);
        if (d == (unsigned)(NBLK - 1)) {          // last to depart resets
            *((volatile unsigned*)&gA[id]) = 0u;
            *((volatile unsigned*)&gD[id]) = 0u;
        }
        __threadfence();
    }
    __syncthreads();
}

// ---- node transform + attention scalars (warp per node, grid-strided) ----------
__device__ void do_transform(Smem* sm, const float* __restrict__ in,
                             const float* __restrict__ W, const float* __restrict__ b,
                             const float* __restrict__ aiw, const float* __restrict__ aib,
                             const float* __restrict__ ajw, const float* __restrict__ ajb,
                             int gwarp, int lane)
{
    int tid = threadIdx.x;
    for (int i = tid; i < IN_CH * IN_CH; i += NTHR) {
        int c = i >> 6, k = i & 63;
        sm->xf.Wt[k * IN_CH + c] = W[i];
    }
    if (tid < IN_CH) { sm->xf.bsh[tid] = b[tid]; sm->xf.ais[tid] = aiw[tid]; sm->xf.ajs[tid] = ajw[tid]; }
    float aib0 = aib[0], ajb0 = ajb[0];
    __syncthreads();

    for (int n = gwarp; n < N_NODES; n += GWARPS) {
        float iv0 = in[(size_t)n * IN_CH + lane];
        float iv1 = in[(size_t)n * IN_CH + 32 + lane];
        float acc0 = sm->xf.bsh[lane], acc1 = sm->xf.bsh[32 + lane];
#pragma unroll
        for (int k = 0; k < 32; k++) {
            float v = __shfl_sync(0xffffffffu, iv0, k);
            acc0 += v * sm->xf.Wt[k * IN_CH + lane];
            acc1 += v * sm->xf.Wt[k * IN_CH + 32 + lane];
        }
#pragma unroll
        for (int k = 0; k < 32; k++) {
            float v = __shfl_sync(0xffffffffu, iv1, k);
            acc0 += v * sm->xf.Wt[(k + 32) * IN_CH + lane];
            acc1 += v * sm->xf.Wt[(k + 32) * IN_CH + 32 + lane];
        }
        g_x[(size_t)n * IN_CH + lane]      = acc0;
        g_x[(size_t)n * IN_CH + 32 + lane] = acc1;

        float ap = acc0 * sm->xf.ais[lane] + acc1 * sm->xf.ais[32 + lane];
        float jp = acc0 * sm->xf.ajs[lane] + acc1 * sm->xf.ajs[32 + lane];
#pragma unroll
        for (int o = 16; o > 0; o >>= 1) {
            ap += __shfl_xor_sync(0xffffffffu, ap, o);
            jp += __shfl_xor_sync(0xffffffffu, jp, o);
        }
        if (lane == 0) { g_ai[n] = ap + aib0; g_aj[n] = jp + ajb0; }
    }
    __syncthreads();
}

// ---- alpha + segment max over src ----------------------------------------------
__device__ void do_alpha_max(const int* __restrict__ src, const int* __restrict__ dst,
                             const float* __restrict__ ew, unsigned* __restrict__ mkey, int gtid)
{
    for (int i = gtid; i < N_EDGES; i += GT) {
        int s = src[i], d = dst[i];
        float a = g_ai[d] + g_aj[s] + ew[i];
        a = a > 0.0f ? a : NEG_SLOPE * a;
        g_alpha[i] = a;
        atomicMax(&mkey[s], fkey(a));
    }
}

// ---- ex = exp(alpha - m[src]); segment sum over src ----------------------------
__device__ void do_exp_sum(const int* __restrict__ src,
                           const unsigned* __restrict__ mkey, float* __restrict__ ssum, int gtid)
{
    for (int i = gtid; i < N_EDGES; i += GT) {
        int s = src[i];
        float m = funkey(mkey[s]);
        float ex = __expf(g_alpha[i] - m);
        g_alpha[i] = ex;
        atomicAdd(&ssum[s], ex);
    }
}

// ---- gather-aggregate per dst node (warp per node, no atomics) ------------------
__device__ void do_gather(Smem* sm, const float* __restrict__ r,
                          const float* __restrict__ relW, const float* __restrict__ relB,
                          const float* __restrict__ ssum, float* __restrict__ out,
                          int gwarp, int lane)
{
    int tid = threadIdx.x;
    for (int i = tid; i < REL_DIM * IN_CH; i += NTHR) {
        int c = i >> 5, k = i & 31;
        sm->gt.Ws[k * IN_CH + c] = relW[i];
    }
    if (tid < IN_CH) sm->gt.Bs[tid] = relB[tid];
    __syncthreads();
    const float2* Ws2 = reinterpret_cast<const float2*>(sm->gt.Ws);
    const float2* Bs2 = reinterpret_cast<const float2*>(sm->gt.Bs);

    for (int node = gwarp; node < N_NODES; node += GWARPS) {
        int start = g_rowst[node];
        int deg   = g_deg[node];

        float2 acc = make_float2(0.f, 0.f);
        float accr = 0.f, csum = 0.f;

        int base = 0;
        for (; base + 32 <= deg; base += 32) {
            int2 se = g_edge[start + base + lane];
            float cf = g_alpha[se.y] / (ssum[se.x] + 1e-16f);
            csum += cf;
#pragma unroll 8
            for (int j = 0; j < 32; j++) {
                float cj = __shfl_sync(0xffffffffu, cf,   j);
                int   sj = __shfl_sync(0xffffffffu, se.x, j);
                int   ej = __shfl_sync(0xffffffffu, se.y, j);
                float2 xv = *reinterpret_cast<const float2*>(g_x + (size_t)sj * IN_CH + 2 * lane);
                acc.x += cj * xv.x;
                acc.y += cj * xv.y;
                accr  += cj * r[(size_t)ej * REL_DIM + lane];
            }
        }
        int m = deg - base;
        if (m > 0) {
            int2 se = make_int2(0, 0);
            float cf = 0.f;
            if (lane < m) {
                se = g_edge[start + base + lane];
                cf = g_alpha[se.y] / (ssum[se.x] + 1e-16f);
            }
            csum += cf;
#pragma unroll 8
            for (int j = 0; j < 32; j++) {
                if (j < m) {
                    float cj = __shfl_sync(0xffffffffu, cf,   j);
                    int   sj = __shfl_sync(0xffffffffu, se.x, j);
                    int   ej = __shfl_sync(0xffffffffu, se.y, j);
                    float2 xv = *reinterpret_cast<const float2*>(g_x + (size_t)sj * IN_CH + 2 * lane);
                    acc.x += cj * xv.x;
                    acc.y += cj * xv.y;
                    accr  += cj * r[(size_t)ej * REL_DIM + lane];
                }
            }
        }

#pragma unroll
        for (int o = 16; o > 0; o >>= 1)
            csum += __shfl_xor_sync(0xffffffffu, csum, o);

        float2 oo = make_float2(0.f, 0.f);
#pragma unroll
        for (int k = 0; k < REL_DIM; k++) {
            float v = __shfl_sync(0xffffffffu, accr, k);
            float2 w = Ws2[k * 32 + lane];
            oo.x += v * w.x;
            oo.y += v * w.y;
        }

        float2 bb = Bs2[lane];
        float r0 = acc.x + oo.x + csum * bb.x;
        float r1 = acc.y + oo.y + csum * bb.y;
        *reinterpret_cast<float2*>(out + (size_t)node * IN_CH + 2 * lane) =
            make_float2(fmaxf(r0, 0.f), fmaxf(r1, 0.f));
    }
    __syncthreads();
}

// =================================================================================
__global__ void __launch_bounds__(NTHR, 4)
k_main(const float* __restrict__ feat, const int* __restrict__ src, const int* __restrict__ dst,
       const float* __restrict__ r, const float* __restrict__ relW, const float* __restrict__ relB,
       const float* c1_lw, const float* c1_lb, const float* c1_aiw, const float* c1_aib,
       const float* c1_ajw, const float* c1_ajb, const float* c1_eww, const float* c1_ewb,
       const float* c2_lw, const float* c2_lb, const float* c2_aiw, const float* c2_aib,
       const float* c2_ajw, const float* c2_ajb, const float* c2_eww, const float* c2_ewb,
       float* __restrict__ out)
{
    __shared__ Smem sm;
    int tid  = threadIdx.x;
    int blk  = blockIdx.x;
    int gtid = blk * NTHR + tid;
    int lane = tid & 31;
    int gwarp = blk * 8 + (tid >> 5);

    // ---------------- P0: init + ewvec ----------------
    for (int i = gtid; i < N_NODES; i += GT) {
        g_deg[i] = 0;
        g_mkey1[i] = 0u; g_ssum1[i] = 0.0f;
        g_mkey2[i] = 0u; g_ssum2[i] = 0.0f;
    }
    if (blk == 0) {
        int t = tid;
        if (t < REL_DIM) {
            float a1 = 0.f, a2 = 0.f;
#pragma unroll
            for (int c = 0; c < IN_CH; c++) {
                float w = relW[c * REL_DIM + t];
                a1 += w * c1_eww[c];
                a2 += w * c2_eww[c];
            }
            g_v1[t] = a1; g_v2[t] = a2;
        } else if (t == 32) {
            float s = 0.f;
            for (int c = 0; c < IN_CH; c++) s += relB[c] * c1_eww[c];
            g_ewc[0] = s + c1_ewb[0];
        } else if (t == 33) {
            float s = 0.f;
            for (int c = 0; c < IN_CH; c++) s += relB[c] * c2_eww[c];
            g_ewc[1] = s + c2_ewb[0];
        }
    }
    gsync(0);

    // ---------------- P1: ew_hist (edges) + transform L1 (nodes) ----------------
    if (tid < REL_DIM) { sm.ew.sv1[tid] = g_v1[tid]; sm.ew.sv2[tid] = g_v2[tid]; }
    if (tid < 2) sm.ew.sc[tid] = g_ewc[tid];
    __syncthreads();
    {
        float c0 = sm.ew.sc[0], c1 = sm.ew.sc[1];
        for (int e = gtid; e < N_EDGES; e += GT) {
            const float4* rp = reinterpret_cast<const float4*>(r + (size_t)e * REL_DIM);
            float a1 = 0.f, a2 = 0.f;
#pragma unroll
            for (int q = 0; q < 8; q++) {
                float4 f = rp[q];
                a1 += f.x * sm.ew.sv1[4*q] + f.y * sm.ew.sv1[4*q+1] + f.z * sm.ew.sv1[4*q+2] + f.w * sm.ew.sv1[4*q+3];
                a2 += f.x * sm.ew.sv2[4*q] + f.y * sm.ew.sv2[4*q+1] + f.z * sm.ew.sv2[4*q+2] + f.w * sm.ew.sv2[4*q+3];
            }
            g_ew1[e] = a1 + c0;
            g_ew2[e] = a2 + c1;
            atomicAdd(&g_deg[dst[e]], 1);
        }
    }
    __syncthreads();
    do_transform(&sm, feat, c1_lw, c1_lb, c1_aiw, c1_aib, c1_ajw, c1_ajb, gwarp, lane);
    gsync(1);

    // ---------------- P2: scan1 (block-local) + alpha_max L1 ----------------
    if (blk < NCHUNK) {
        int i = blk * 256 + tid;
        int v = (i < N_NODES) ? g_deg[i] : 0;
        int x = v;
#pragma unroll
        for (int off = 1; off < 32; off <<= 1) {
            int y = __shfl_up_sync(0xffffffffu, x, off);
            if (lane >= off) x += y;
        }
        int wid = tid >> 5;
        if (lane == 31) sm.sc.wsum[wid] = x;
        __syncthreads();
        if (wid == 0) {
            int s = (lane < 8) ? sm.sc.wsum[lane] : 0;
#pragma unroll
            for (int off = 1; off < 8; off <<= 1) {
                int y = __shfl_up_sync(0xffffffffu, s, off);
                if (lane >= off) s += y;
            }
            if (lane < 8) sm.sc.wsum[lane] = s;
        }
        __syncthreads();
        int woff = (wid == 0) ? 0 : sm.sc.wsum[wid - 1];
        if (i < N_NODES) g_rowst[i] = woff + x - v;
        if (tid == 255) g_bsum[blk] = woff + x;
        __syncthreads();
    }
    do_alpha_max(src, dst, g_ew1, g_mkey1, gtid);
    gsync(2);

    // ---------------- P3: scan2 (block 0) + exp_sum L1 ----------------
    if (blk == 0) {
        int t = tid, wid = t >> 5;
        int v = (t < NCHUNK) ? g_bsum[t] : 0;
        int x = v;
#pragma unroll
        for (int off = 1; off < 32; off <<= 1) {
            int y = __shfl_up_sync(0xffffffffu, x, off);
            if (lane >= off) x += y;
        }
        if (lane == 31) sm.sc.wsum[wid] = x;
        __syncthreads();
        if (wid == 0) {
            int s = (lane < 8) ? sm.sc.wsum[lane] : 0;
#pragma unroll
            for (int off = 1; off < 8; off <<= 1) {
                int y = __shfl_up_sync(0xffffffffu, s, off);
                if (lane >= off) s += y;
            }
            if (lane < 8) sm.sc.wsum[lane] = s;
        }
        __syncthreads();
        int woff = (wid == 0) ? 0 : sm.sc.wsum[wid - 1];
        if (t < NCHUNK) g_boff[t] = woff + x - v;
        __syncthreads();
    }
    do_exp_sum(src, g_mkey1, g_ssum1, gtid);
    gsync(3);

    // ---------------- P4: scan3 ----------------
    for (int i = gtid; i < N_NODES; i += GT) {
        int v = g_rowst[i] + g_boff[i >> 8];
        g_rowst[i] = v;
        g_curs[i]  = v;
    }
    gsync(4);

    // ---------------- P5: scatter ----------------
    for (int i = gtid; i < N_EDGES; i += GT) {
        int p = atomicAdd(&g_curs[dst[i]], 1);
        g_edge[p] = make_int2(src[i], i);
    }
    gsync(5);

    // ---------------- P6: gather L1 -> g_h ----------------
    do_gather(&sm, r, relW, relB, g_ssum1, g_h, gwarp, lane);
    gsync(6);

    // ---------------- P7: transform L2 ----------------
    do_transform(&sm, g_h, c2_lw, c2_lb, c2_aiw, c2_aib, c2_ajw, c2_ajb, gwarp, lane);
    gsync(7);

    // ---------------- P8: alpha_max L2 ----------------
    do_alpha_max(src, dst, g_ew2, g_mkey2, gtid);
    gsync(8);

    // ---------------- P9: exp_sum L2 ----------------
    do_exp_sum(src, g_mkey2, g_ssum2, gtid);
    gsync(9);

    // ---------------- P10: gather L2 -> out ----------------
    do_gather(&sm, r, relW, relB, g_ssum2, out, gwarp, lane);
}

extern "C" void kernel_launch(void* const* d_in, const int* in_sizes, int n_in,
                              void* d_out, int out_size)
{
    const float* feat   = (const float*)d_in[0];
    const int*   eidx   = (const int*)  d_in[1];
    const float* r      = (const float*)d_in[2];
    const float* rel_w  = (const float*)d_in[3];
    const float* rel_b  = (const float*)d_in[4];
    const float* c1_lw  = (const float*)d_in[5];
    const float* c1_lb  = (const float*)d_in[6];
    const float* c1_aiw = (const float*)d_in[7];
    const float* c1_aib = (const float*)d_in[8];
    const float* c1_ajw = (const float*)d_in[9];
    const float* c1_ajb = (const float*)d_in[10];
    const float* c1_eww = (const float*)d_in[11];
    const float* c1_ewb = (const float*)d_in[12];
    const float* c2_lw  = (const float*)d_in[13];
    const float* c2_lb  = (const float*)d_in[14];
    const float* c2_aiw = (const float*)d_in[15];
    const float* c2_aib = (const float*)d_in[16];
    const float* c2_ajw = (const float*)d_in[17];
    const float* c2_ajb = (const float*)d_in[18];
    const float* c2_eww = (const float*)d_in[19];
    const float* c2_ewb = (const float*)d_in[20];
    float* out = (float*)d_out;

    const int* src = eidx;
    const int* dst = eidx + N_EDGES;

    k_main<<<NBLK, NTHR>>>(feat, src, dst, r, rel_w, rel_b,
                           c1_lw, c1_lb, c1_aiw, c1_aib, c1_ajw, c1_ajb, c1_eww, c1_ewb,
                           c2_lw, c2_lb, c2_aiw, c2_aib, c2_ajw, c2_ajb, c2_eww, c2_ewb,
                           out);
}